// round 9
// baseline (speedup 1.0000x reference)
#include <cuda_runtime.h>
#include <cuda_fp16.h>
#include <mma.h>
using namespace nvcuda;

#define MAX_N 20000
#define MAX_E 5000
#define FT 128
#define NODE_CAP 128   // max edges per node (mean ~50, 11 sigma headroom)
#define EDGE_CAP 384   // max nodes per edge (mean ~200, 13 sigma headroom)
#define LIST_CAP 192   // per-row staging list (mean 50, 20 sigma headroom)
#define EPB 16         // edges per block in gather_mma

// ---- scratch (__device__ globals; no allocations allowed) ----
__device__ int    g_dv[MAX_N];               // node degree
__device__ int    g_de[MAX_E];               // edge degree
__device__ int    g_csr[MAX_N * NODE_CAP];   // edges per node
__device__ int    g_csc[MAX_E * EDGE_CAP];   // nodes per edge
__device__ __align__(16) __half g_Xh[MAX_N * FT];  // X in fp16
__device__ __align__(16) __half g_Wh[FT * FT];     // W in fp16
__device__ __align__(16) __half g_Mh[MAX_E * FT];  // M in fp16

// ---------------------------------------------------------------------------
// Fused: zero degree counters + convert X and W to fp16.
__global__ void prep(const float* __restrict__ X, const float* __restrict__ W,
                     int x4, int w4, int n_nodes, int n_edges) {
    int i = blockIdx.x * blockDim.x + threadIdx.x;
    if (i < n_nodes) g_dv[i] = 0;
    if (i < n_edges) g_de[i] = 0;
    if (i < x4) {
        float4 v = ((const float4*)X)[i];
        __half2 a = __floats2half2_rn(v.x, v.y);
        __half2 b = __floats2half2_rn(v.z, v.w);
        uint2 p; p.x = *(unsigned*)&a; p.y = *(unsigned*)&b;
        ((uint2*)g_Xh)[i] = p;
    } else if (i < x4 + w4) {
        int j = i - x4;
        float4 v = ((const float4*)W)[j];
        __half2 a = __floats2half2_rn(v.x, v.y);
        __half2 b = __floats2half2_rn(v.z, v.w);
        uint2 p; p.x = *(unsigned*)&a; p.y = *(unsigned*)&b;
        ((uint2*)g_Wh)[j] = p;
    }
}

// One block per node row of H; reads 400MB exactly once (streaming).
// NOTE: no min-blocks clause — a (256,8) bound forced a 32-reg ceiling that
// serialized the 4-load batch (same defect as R4's gather_mma). DRAM-latency
// hiding here needs real per-thread MLP=4, i.e. ~48 regs.
__global__ __launch_bounds__(256) void build_sparse(const float* __restrict__ H,
                                                    int n_edges) {
    int n = blockIdx.x;
    __shared__ int s_cnt;
    __shared__ int s_list[LIST_CAP];
    if (threadIdx.x == 0) s_cnt = 0;
    __syncthreads();

    const float4* row = (const float4*)(H + (size_t)n * n_edges);
    int nq = n_edges >> 2;
    int lane = threadIdx.x & 31;
    const float4 z4 = make_float4(0.f, 0.f, 0.f, 0.f);

    int stride = 4 * blockDim.x;
    int iters = (nq + stride - 1) / stride;   // uniform across the block

    for (int it = 0; it < iters; it++) {
        int i0 = threadIdx.x + it * stride;
        int i1 = i0 + blockDim.x;
        int i2 = i0 + 2 * blockDim.x;
        int i3 = i0 + 3 * blockDim.x;
        float4 v0 = (i0 < nq) ? __ldcs(&row[i0]) : z4;
        float4 v1 = (i1 < nq) ? __ldcs(&row[i1]) : z4;
        float4 v2 = (i2 < nq) ? __ldcs(&row[i2]) : z4;
        float4 v3 = (i3 < nq) ? __ldcs(&row[i3]) : z4;

        // per-thread nonzero count (branch-free)
        int c = (v0.x != 0.f) + (v0.y != 0.f) + (v0.z != 0.f) + (v0.w != 0.f)
              + (v1.x != 0.f) + (v1.y != 0.f) + (v1.z != 0.f) + (v1.w != 0.f)
              + (v2.x != 0.f) + (v2.y != 0.f) + (v2.z != 0.f) + (v2.w != 0.f)
              + (v3.x != 0.f) + (v3.y != 0.f) + (v3.z != 0.f) + (v3.w != 0.f);

        // warp inclusive scan of c (all 32 lanes always active)
        int pre = c;
        #pragma unroll
        for (int d = 1; d < 32; d <<= 1) {
            int t = __shfl_up_sync(0xffffffffu, pre, d);
            if (lane >= d) pre += t;
        }
        int total = __shfl_sync(0xffffffffu, pre, 31);
        if (total) {
            int base = 0;
            if (lane == 31) base = atomicAdd(&s_cnt, total);
            base = __shfl_sync(0xffffffffu, base, 31);
            int p = base + pre - c;   // exclusive offset for this lane
            #define EMIT(vv, ii) do { \
                int eb = (ii) << 2; \
                if ((vv).x != 0.f) { if (p < LIST_CAP) s_list[p] = eb;     p++; } \
                if ((vv).y != 0.f) { if (p < LIST_CAP) s_list[p] = eb + 1; p++; } \
                if ((vv).z != 0.f) { if (p < LIST_CAP) s_list[p] = eb + 2; p++; } \
                if ((vv).w != 0.f) { if (p < LIST_CAP) s_list[p] = eb + 3; p++; } \
            } while (0)
            EMIT(v0, i0); EMIT(v1, i1); EMIT(v2, i2); EMIT(v3, i3);
            #undef EMIT
        }
    }
    __syncthreads();

    int cnt = min(s_cnt, LIST_CAP);
    if (threadIdx.x == 0) g_dv[n] = min(cnt, NODE_CAP);
    for (int t = threadIdx.x; t < cnt; t += blockDim.x) {
        int e = s_list[t];
        if (t < NODE_CAP) g_csr[n * NODE_CAP + t] = e;
        int q = atomicAdd(&g_de[e], 1);
        if (q < EDGE_CAP) g_csc[e * EDGE_CAP + q] = n;
    }
}

// 16 edges per block. Phase 1: warp w gathers S[w] with 4 independent
// LDG.128 in flight per lane (launch_bounds(512,2) -> 64-reg budget).
// Phase 2: HMMA projection. Phase 3: /DE, store fp16.
__global__ __launch_bounds__(512, 2) void gather_mma(int n_edges) {
    __shared__ __half s_h[EPB][FT];
    __shared__ float  s_C[EPB][FT];

    int w = threadIdx.x >> 5;
    int lane = threadIdx.x & 31;
    int e0 = blockIdx.x * EPB;
    int e = e0 + w;

    // ---- phase 1: gather ----
    int hw = lane >> 4;        // half-warp -> node parity
    int fl = lane & 15;        // feature lane: 8 features
    if (e < n_edges) {
        int cnt = min(g_de[e], EDGE_CAP);
        const int* __restrict__ nodes = g_csc + e * EDGE_CAP;
        float acc[8];
        #pragma unroll
        for (int j = 0; j < 8; j++) acc[j] = 0.f;

        int i = hw;
        for (; i + 8 <= cnt; i += 8) {   // 4 nodes per half-warp per iter
            int n0 = nodes[i];
            int n1 = nodes[i + 2];
            int n2 = nodes[i + 4];
            int n3 = nodes[i + 6];
            uint4 p0 = ((const uint4*)(g_Xh + (size_t)n0 * FT))[fl];
            uint4 p1 = ((const uint4*)(g_Xh + (size_t)n1 * FT))[fl];
            uint4 p2 = ((const uint4*)(g_Xh + (size_t)n2 * FT))[fl];
            uint4 p3 = ((const uint4*)(g_Xh + (size_t)n3 * FT))[fl];
            __half2* h0 = (__half2*)&p0;
            __half2* h1 = (__half2*)&p1;
            __half2* h2 = (__half2*)&p2;
            __half2* h3 = (__half2*)&p3;
            #pragma unroll
            for (int q = 0; q < 4; q++) {
                float2 f0 = __half22float2(h0[q]);
                float2 f1 = __half22float2(h1[q]);
                float2 f2 = __half22float2(h2[q]);
                float2 f3 = __half22float2(h3[q]);
                acc[2 * q]     += (f0.x + f1.x) + (f2.x + f3.x);
                acc[2 * q + 1] += (f0.y + f1.y) + (f2.y + f3.y);
            }
        }
        for (; i < cnt; i += 2) {
            int n = nodes[i];
            uint4 p = ((const uint4*)(g_Xh + (size_t)n * FT))[fl];
            __half2* hp = (__half2*)&p;
            #pragma unroll
            for (int q = 0; q < 4; q++) {
                float2 f = __half22float2(hp[q]);
                acc[2 * q]     += f.x;
                acc[2 * q + 1] += f.y;
            }
        }
        #pragma unroll
        for (int j = 0; j < 8; j++)
            acc[j] += __shfl_xor_sync(0xffffffffu, acc[j], 16);
        if (hw == 0) {
            uint4 o;
            __half2 h0 = __floats2half2_rn(acc[0], acc[1]);
            __half2 h1 = __floats2half2_rn(acc[2], acc[3]);
            __half2 h2 = __floats2half2_rn(acc[4], acc[5]);
            __half2 h3 = __floats2half2_rn(acc[6], acc[7]);
            o.x = *(unsigned*)&h0; o.y = *(unsigned*)&h1;
            o.z = *(unsigned*)&h2; o.w = *(unsigned*)&h3;
            ((uint4*)&s_h[w][0])[fl] = o;
        }
    } else {
        if (lane < 16) ((uint4*)&s_h[w][0])[lane] = make_uint4(0, 0, 0, 0);
    }
    __syncthreads();

    // ---- phase 2: [16,128] x [128,128] HMMA ----
    if (w < 8) {
        wmma::fragment<wmma::accumulator, 16, 16, 16, float> c;
        wmma::fill_fragment(c, 0.f);
        #pragma unroll
        for (int k = 0; k < FT; k += 16) {
            wmma::fragment<wmma::matrix_a, 16, 16, 16, __half, wmma::row_major> a;
            wmma::fragment<wmma::matrix_b, 16, 16, 16, __half, wmma::row_major> b;
            wmma::load_matrix_sync(a, &s_h[0][k], FT);
            wmma::load_matrix_sync(b, g_Wh + k * FT + w * 16, FT);
            wmma::mma_sync(c, a, b, c);
        }
        wmma::store_matrix_sync(&s_C[0][w * 16], c, FT, wmma::mem_row_major);
    }
    __syncthreads();

    // ---- phase 3: epilogue M = C / DE ----
    for (int idx = threadIdx.x; idx < EPB * FT; idx += 512) {
        int r = idx >> 7, j = idx & (FT - 1);
        int e2 = e0 + r;
        if (e2 < n_edges) {
            int de = g_de[e2];
            float m = (de > 0) ? s_C[r][j] / (float)de : 0.f;
            g_Mh[(size_t)e2 * FT + j] = __float2half(m);
        }
    }
}

// out[n] = relu( (sum_{e in node n} M[e]) / dv[n] + bias ).
// NOTE: no min-blocks bound — regs=32 / 16 blocks/SM measured 30.4-30.9us;
// capping to 8 blocks (regs=60) measured 45.6us. Warp count wins here.
__global__ __launch_bounds__(FT) void scatter_out(const float* __restrict__ bias,
                                                  float* __restrict__ out) {
    int n = blockIdx.x;
    int t = threadIdx.x;
    int lane = t & 31;
    int g = t >> 5;
    int cnt = g_dv[n];
    const int* __restrict__ edges = g_csr + n * NODE_CAP;

    float4 acc = make_float4(0.f, 0.f, 0.f, 0.f);
    int i = g;
    for (; i + 16 <= cnt; i += 16) {   // 4 edges per group per iter
        int e0 = edges[i];
        int e1 = edges[i + 4];
        int e2 = edges[i + 8];
        int e3 = edges[i + 12];
        uint2 p0 = ((const uint2*)(g_Mh + (size_t)e0 * FT))[lane];
        uint2 p1 = ((const uint2*)(g_Mh + (size_t)e1 * FT))[lane];
        uint2 p2 = ((const uint2*)(g_Mh + (size_t)e2 * FT))[lane];
        uint2 p3 = ((const uint2*)(g_Mh + (size_t)e3 * FT))[lane];
        float2 a0 = __half22float2(*(__half2*)&p0.x), b0 = __half22float2(*(__half2*)&p0.y);
        float2 a1 = __half22float2(*(__half2*)&p1.x), b1 = __half22float2(*(__half2*)&p1.y);
        float2 a2 = __half22float2(*(__half2*)&p2.x), b2 = __half22float2(*(__half2*)&p2.y);
        float2 a3 = __half22float2(*(__half2*)&p3.x), b3 = __half22float2(*(__half2*)&p3.y);
        acc.x += (a0.x + a1.x) + (a2.x + a3.x);
        acc.y += (a0.y + a1.y) + (a2.y + a3.y);
        acc.z += (b0.x + b1.x) + (b2.x + b3.x);
        acc.w += (b0.y + b1.y) + (b2.y + b3.y);
    }
    for (; i < cnt; i += 4) {
        int e = edges[i];
        uint2 p = ((const uint2*)(g_Mh + (size_t)e * FT))[lane];
        float2 f0 = __half22float2(*(__half2*)&p.x);
        float2 f1 = __half22float2(*(__half2*)&p.y);
        acc.x += f0.x; acc.y += f0.y; acc.z += f1.x; acc.w += f1.y;
    }

    __shared__ float part[4][FT];
    ((float4*)part[g])[lane] = acc;
    __syncthreads();
    float v = (part[0][t] + part[1][t]) + (part[2][t] + part[3][t]);
    v = (cnt > 0) ? v / (float)cnt : 0.f;
    v += bias[t];
    out[(size_t)n * FT + t] = v > 0.f ? v : 0.f;
}

// ---------------------------------------------------------------------------
extern "C" void kernel_launch(void* const* d_in, const int* in_sizes, int n_in,
                              void* d_out, int out_size) {
    const float* X  = (const float*)d_in[0];   // [N, 128]
    const float* H  = (const float*)d_in[1];   // [N, E]
    const float* Wt = (const float*)d_in[2];   // [128, 128]
    const float* bs = (const float*)d_in[3];   // [128]
    float* out = (float*)d_out;                // [N, 128]

    int n_nodes = in_sizes[0] / FT;            // 20000
    int n_edges = in_sizes[1] / n_nodes;       // 5000
    if (n_nodes > MAX_N) n_nodes = MAX_N;
    if (n_edges > MAX_E) n_edges = MAX_E;

    int x4 = n_nodes * FT / 4;
    int w4 = FT * FT / 4;
    int ptot = x4 + w4;
    if (n_nodes > ptot) ptot = n_nodes;
    prep<<<(ptot + 255) / 256, 256>>>(X, Wt, x4, w4, n_nodes, n_edges);
    build_sparse<<<n_nodes, 256>>>(H, n_edges);
    gather_mma<<<(n_edges + EPB - 1) / EPB, 512>>>(n_edges);
    scatter_out<<<n_nodes, FT>>>(bs, out);
}

// round 10
// speedup vs baseline: 1.0448x; 1.0448x over previous
#include <cuda_runtime.h>
#include <cuda_fp16.h>
#include <mma.h>
using namespace nvcuda;

#define MAX_N 20000
#define MAX_E 5000
#define FT 128
#define NODE_CAP 128   // max edges per node (mean ~50, 11 sigma headroom)
#define EDGE_CAP 384   // max nodes per edge (mean ~200, 13 sigma headroom)
#define LIST_CAP 192   // per-row staging list (mean 50, 20 sigma headroom)
#define EPB 16         // edges per block in gather_mma
#define BW 8           // warps (rows) per build block

// ---- scratch (__device__ globals; no allocations allowed) ----
__device__ int    g_dv[MAX_N];               // node degree
__device__ int    g_de[MAX_E];               // edge degree
__device__ int    g_csr[MAX_N * NODE_CAP];   // edges per node
__device__ int    g_csc[MAX_E * EDGE_CAP];   // nodes per edge
__device__ __align__(16) __half g_Xh[MAX_N * FT];  // X in fp16
__device__ __align__(16) __half g_Wh[FT * FT];     // W in fp16
__device__ __align__(16) __half g_Mh[MAX_E * FT];  // M in fp16

// ---------------------------------------------------------------------------
// Fused: zero degree counters + convert X and W to fp16.
__global__ void prep(const float* __restrict__ X, const float* __restrict__ W,
                     int x4, int w4, int n_nodes, int n_edges) {
    int i = blockIdx.x * blockDim.x + threadIdx.x;
    if (i < n_nodes) g_dv[i] = 0;
    if (i < n_edges) g_de[i] = 0;
    if (i < x4) {
        float4 v = ((const float4*)X)[i];
        __half2 a = __floats2half2_rn(v.x, v.y);
        __half2 b = __floats2half2_rn(v.z, v.w);
        uint2 p; p.x = *(unsigned*)&a; p.y = *(unsigned*)&b;
        ((uint2*)g_Xh)[i] = p;
    } else if (i < x4 + w4) {
        int j = i - x4;
        float4 v = ((const float4*)W)[j];
        __half2 a = __floats2half2_rn(v.x, v.y);
        __half2 b = __floats2half2_rn(v.z, v.w);
        uint2 p; p.x = *(unsigned*)&a; p.y = *(unsigned*)&b;
        ((uint2*)g_Wh)[j] = p;
    }
}

// ONE WARP PER ROW of H: no block barriers, sustained load stream per warp
// (10 iterations x 4 predicated LDG.128), warp-local scan/emit into a private
// smem list, warp-local drain. Reads 400MB exactly once (streaming).
__global__ __launch_bounds__(32 * BW) void build_sparse(const float* __restrict__ H,
                                                        int n_nodes, int n_edges) {
    __shared__ int s_list[BW][LIST_CAP];
    int wid = threadIdx.x >> 5;
    int lane = threadIdx.x & 31;
    int n = blockIdx.x * BW + wid;           // row = node id (uniform per warp)
    if (n >= n_nodes) return;
    int* list = s_list[wid];

    const float4* row = (const float4*)(H + (size_t)n * n_edges);
    int nq = n_edges >> 2;                   // 1250
    const float4 z4 = make_float4(0.f, 0.f, 0.f, 0.f);

    int cnt = 0;                             // kept uniform across the warp
    int iters = (nq + 127) / 128;            // warp covers 128 quads per iter

    for (int it = 0; it < iters; it++) {
        int i0 = it * 128 + lane;
        int i1 = i0 + 32;
        int i2 = i0 + 64;
        int i3 = i0 + 96;
        float4 v0 = (i0 < nq) ? __ldcs(&row[i0]) : z4;
        float4 v1 = (i1 < nq) ? __ldcs(&row[i1]) : z4;
        float4 v2 = (i2 < nq) ? __ldcs(&row[i2]) : z4;
        float4 v3 = (i3 < nq) ? __ldcs(&row[i3]) : z4;

        int c = (v0.x != 0.f) + (v0.y != 0.f) + (v0.z != 0.f) + (v0.w != 0.f)
              + (v1.x != 0.f) + (v1.y != 0.f) + (v1.z != 0.f) + (v1.w != 0.f)
              + (v2.x != 0.f) + (v2.y != 0.f) + (v2.z != 0.f) + (v2.w != 0.f)
              + (v3.x != 0.f) + (v3.y != 0.f) + (v3.z != 0.f) + (v3.w != 0.f);

        // warp inclusive scan (all lanes active, uniform trip count)
        int pre = c;
        #pragma unroll
        for (int d = 1; d < 32; d <<= 1) {
            int t = __shfl_up_sync(0xffffffffu, pre, d);
            if (lane >= d) pre += t;
        }
        int total = __shfl_sync(0xffffffffu, pre, 31);
        if (total) {                          // uniform branch
            int p = cnt + pre - c;            // exclusive offset for this lane
            #define EMIT(vv, ii) do { \
                int eb = (ii) << 2; \
                if ((vv).x != 0.f) { if (p < LIST_CAP) list[p] = eb;     p++; } \
                if ((vv).y != 0.f) { if (p < LIST_CAP) list[p] = eb + 1; p++; } \
                if ((vv).z != 0.f) { if (p < LIST_CAP) list[p] = eb + 2; p++; } \
                if ((vv).w != 0.f) { if (p < LIST_CAP) list[p] = eb + 3; p++; } \
            } while (0)
            EMIT(v0, i0); EMIT(v1, i1); EMIT(v2, i2); EMIT(v3, i3);
            #undef EMIT
        }
        cnt += total;                         // stays uniform
    }
    __syncwarp();

    cnt = min(cnt, LIST_CAP);
    if (lane == 0) g_dv[n] = min(cnt, NODE_CAP);
    for (int t = lane; t < cnt; t += 32) {
        int e = list[t];
        if (t < NODE_CAP) g_csr[n * NODE_CAP + t] = e;
        int q = atomicAdd(&g_de[e], 1);
        if (q < EDGE_CAP) g_csc[e * EDGE_CAP + q] = n;
    }
}

// 16 edges per block. Phase 1: warp w gathers S[w] with 4 independent
// LDG.128 in flight per lane (launch_bounds(512,2) -> 64-reg budget).
// Phase 2: HMMA projection. Phase 3: /DE, store fp16.
__global__ __launch_bounds__(512, 2) void gather_mma(int n_edges) {
    __shared__ __half s_h[EPB][FT];
    __shared__ float  s_C[EPB][FT];

    int w = threadIdx.x >> 5;
    int lane = threadIdx.x & 31;
    int e0 = blockIdx.x * EPB;
    int e = e0 + w;

    // ---- phase 1: gather ----
    int hw = lane >> 4;        // half-warp -> node parity
    int fl = lane & 15;        // feature lane: 8 features
    if (e < n_edges) {
        int cnt = min(g_de[e], EDGE_CAP);
        const int* __restrict__ nodes = g_csc + e * EDGE_CAP;
        float acc[8];
        #pragma unroll
        for (int j = 0; j < 8; j++) acc[j] = 0.f;

        int i = hw;
        for (; i + 8 <= cnt; i += 8) {   // 4 nodes per half-warp per iter
            int n0 = nodes[i];
            int n1 = nodes[i + 2];
            int n2 = nodes[i + 4];
            int n3 = nodes[i + 6];
            uint4 p0 = ((const uint4*)(g_Xh + (size_t)n0 * FT))[fl];
            uint4 p1 = ((const uint4*)(g_Xh + (size_t)n1 * FT))[fl];
            uint4 p2 = ((const uint4*)(g_Xh + (size_t)n2 * FT))[fl];
            uint4 p3 = ((const uint4*)(g_Xh + (size_t)n3 * FT))[fl];
            __half2* h0 = (__half2*)&p0;
            __half2* h1 = (__half2*)&p1;
            __half2* h2 = (__half2*)&p2;
            __half2* h3 = (__half2*)&p3;
            #pragma unroll
            for (int q = 0; q < 4; q++) {
                float2 f0 = __half22float2(h0[q]);
                float2 f1 = __half22float2(h1[q]);
                float2 f2 = __half22float2(h2[q]);
                float2 f3 = __half22float2(h3[q]);
                acc[2 * q]     += (f0.x + f1.x) + (f2.x + f3.x);
                acc[2 * q + 1] += (f0.y + f1.y) + (f2.y + f3.y);
            }
        }
        for (; i < cnt; i += 2) {
            int n = nodes[i];
            uint4 p = ((const uint4*)(g_Xh + (size_t)n * FT))[fl];
            __half2* hp = (__half2*)&p;
            #pragma unroll
            for (int q = 0; q < 4; q++) {
                float2 f = __half22float2(hp[q]);
                acc[2 * q]     += f.x;
                acc[2 * q + 1] += f.y;
            }
        }
        #pragma unroll
        for (int j = 0; j < 8; j++)
            acc[j] += __shfl_xor_sync(0xffffffffu, acc[j], 16);
        if (hw == 0) {
            uint4 o;
            __half2 h0 = __floats2half2_rn(acc[0], acc[1]);
            __half2 h1 = __floats2half2_rn(acc[2], acc[3]);
            __half2 h2 = __floats2half2_rn(acc[4], acc[5]);
            __half2 h3 = __floats2half2_rn(acc[6], acc[7]);
            o.x = *(unsigned*)&h0; o.y = *(unsigned*)&h1;
            o.z = *(unsigned*)&h2; o.w = *(unsigned*)&h3;
            ((uint4*)&s_h[w][0])[fl] = o;
        }
    } else {
        if (lane < 16) ((uint4*)&s_h[w][0])[lane] = make_uint4(0, 0, 0, 0);
    }
    __syncthreads();

    // ---- phase 2: [16,128] x [128,128] HMMA ----
    if (w < 8) {
        wmma::fragment<wmma::accumulator, 16, 16, 16, float> c;
        wmma::fill_fragment(c, 0.f);
        #pragma unroll
        for (int k = 0; k < FT; k += 16) {
            wmma::fragment<wmma::matrix_a, 16, 16, 16, __half, wmma::row_major> a;
            wmma::fragment<wmma::matrix_b, 16, 16, 16, __half, wmma::row_major> b;
            wmma::load_matrix_sync(a, &s_h[0][k], FT);
            wmma::load_matrix_sync(b, g_Wh + k * FT + w * 16, FT);
            wmma::mma_sync(c, a, b, c);
        }
        wmma::store_matrix_sync(&s_C[0][w * 16], c, FT, wmma::mem_row_major);
    }
    __syncthreads();

    // ---- phase 3: epilogue M = C / DE ----
    for (int idx = threadIdx.x; idx < EPB * FT; idx += 512) {
        int r = idx >> 7, j = idx & (FT - 1);
        int e2 = e0 + r;
        if (e2 < n_edges) {
            int de = g_de[e2];
            float m = (de > 0) ? s_C[r][j] / (float)de : 0.f;
            g_Mh[(size_t)e2 * FT + j] = __float2half(m);
        }
    }
}

// out[n] = relu( (sum_{e in node n} M[e]) / dv[n] + bias ).
// NOTE: no min-blocks bound — regs=32 / 16 blocks/SM measured 30.2-30.9us;
// capping to 8 blocks (regs=60) measured 45.6us. Warp count wins here.
__global__ __launch_bounds__(FT) void scatter_out(const float* __restrict__ bias,
                                                  float* __restrict__ out) {
    int n = blockIdx.x;
    int t = threadIdx.x;
    int lane = t & 31;
    int g = t >> 5;
    int cnt = g_dv[n];
    const int* __restrict__ edges = g_csr + n * NODE_CAP;

    float4 acc = make_float4(0.f, 0.f, 0.f, 0.f);
    int i = g;
    for (; i + 16 <= cnt; i += 16) {   // 4 edges per group per iter
        int e0 = edges[i];
        int e1 = edges[i + 4];
        int e2 = edges[i + 8];
        int e3 = edges[i + 12];
        uint2 p0 = ((const uint2*)(g_Mh + (size_t)e0 * FT))[lane];
        uint2 p1 = ((const uint2*)(g_Mh + (size_t)e1 * FT))[lane];
        uint2 p2 = ((const uint2*)(g_Mh + (size_t)e2 * FT))[lane];
        uint2 p3 = ((const uint2*)(g_Mh + (size_t)e3 * FT))[lane];
        float2 a0 = __half22float2(*(__half2*)&p0.x), b0 = __half22float2(*(__half2*)&p0.y);
        float2 a1 = __half22float2(*(__half2*)&p1.x), b1 = __half22float2(*(__half2*)&p1.y);
        float2 a2 = __half22float2(*(__half2*)&p2.x), b2 = __half22float2(*(__half2*)&p2.y);
        float2 a3 = __half22float2(*(__half2*)&p3.x), b3 = __half22float2(*(__half2*)&p3.y);
        acc.x += (a0.x + a1.x) + (a2.x + a3.x);
        acc.y += (a0.y + a1.y) + (a2.y + a3.y);
        acc.z += (b0.x + b1.x) + (b2.x + b3.x);
        acc.w += (b0.y + b1.y) + (b2.y + b3.y);
    }
    for (; i < cnt; i += 4) {
        int e = edges[i];
        uint2 p = ((const uint2*)(g_Mh + (size_t)e * FT))[lane];
        float2 f0 = __half22float2(*(__half2*)&p.x);
        float2 f1 = __half22float2(*(__half2*)&p.y);
        acc.x += f0.x; acc.y += f0.y; acc.z += f1.x; acc.w += f1.y;
    }

    __shared__ float part[4][FT];
    ((float4*)part[g])[lane] = acc;
    __syncthreads();
    float v = (part[0][t] + part[1][t]) + (part[2][t] + part[3][t]);
    v = (cnt > 0) ? v / (float)cnt : 0.f;
    v += bias[t];
    out[(size_t)n * FT + t] = v > 0.f ? v : 0.f;
}

// ---------------------------------------------------------------------------
extern "C" void kernel_launch(void* const* d_in, const int* in_sizes, int n_in,
                              void* d_out, int out_size) {
    const float* X  = (const float*)d_in[0];   // [N, 128]
    const float* H  = (const float*)d_in[1];   // [N, E]
    const float* Wt = (const float*)d_in[2];   // [128, 128]
    const float* bs = (const float*)d_in[3];   // [128]
    float* out = (float*)d_out;                // [N, 128]

    int n_nodes = in_sizes[0] / FT;            // 20000
    int n_edges = in_sizes[1] / n_nodes;       // 5000
    if (n_nodes > MAX_N) n_nodes = MAX_N;
    if (n_edges > MAX_E) n_edges = MAX_E;

    int x4 = n_nodes * FT / 4;
    int w4 = FT * FT / 4;
    int ptot = x4 + w4;
    if (n_nodes > ptot) ptot = n_nodes;
    prep<<<(ptot + 255) / 256, 256>>>(X, Wt, x4, w4, n_nodes, n_edges);
    build_sparse<<<(n_nodes + BW - 1) / BW, 32 * BW>>>(H, n_nodes, n_edges);
    gather_mma<<<(n_edges + EPB - 1) / EPB, 512>>>(n_edges);
    scatter_out<<<n_nodes, FT>>>(bs, out);
}

// round 12
// speedup vs baseline: 1.0609x; 1.0154x over previous
#include <cuda_runtime.h>
#include <cuda_fp16.h>
#include <cstdint>
#include <mma.h>
using namespace nvcuda;

#define MAX_N 20000
#define MAX_E 5000
#define FT 128
#define NODE_CAP 128   // max edges per node (mean ~50, 11 sigma headroom)
#define EDGE_CAP 384   // max nodes per edge (mean ~200, 13 sigma headroom)
#define LIST_CAP 192   // per-row staging list (mean 50, 20 sigma headroom)
#define EPB 16         // edges per block in gather_mma

// ---- scratch (__device__ globals; no allocations allowed) ----
__device__ int    g_dv[MAX_N];               // node degree
__device__ int    g_de[MAX_E];               // edge degree
__device__ int    g_csr[MAX_N * NODE_CAP];   // edges per node
__device__ int    g_csc[MAX_E * EDGE_CAP];   // nodes per edge
__device__ __align__(16) __half g_Xh[MAX_N * FT];  // X in fp16
__device__ __align__(16) __half g_Wh[FT * FT];     // W in fp16
__device__ __align__(16) __half g_Mh[MAX_E * FT];  // M in fp16

__device__ __forceinline__ uint32_t smem_u32(const void* p) {
    uint32_t a;
    asm("{ .reg .u64 t; cvta.to.shared.u64 t, %1; cvt.u32.u64 %0, t; }"
        : "=r"(a) : "l"(p));
    return a;
}

__device__ __forceinline__ void mbar_wait_parity(uint32_t mbar, uint32_t parity) {
    uint32_t done;
    asm volatile(
        "{\n\t.reg .pred p;\n\t"
        "mbarrier.try_wait.parity.acquire.cta.shared::cta.b64 p, [%1], %2;\n\t"
        "selp.b32 %0, 1, 0, p;\n\t}"
        : "=r"(done) : "r"(mbar), "r"(parity) : "memory");
    if (!done) {
        asm volatile(
            "{\n\t.reg .pred P1;\n\t"
            "WAIT_LOOP_%=:\n\t"
            "mbarrier.try_wait.parity.acquire.cta.shared::cta.b64 P1, [%0], %1, 0x989680;\n\t"
            "@P1 bra.uni WAIT_DONE_%=;\n\t"
            "bra.uni WAIT_LOOP_%=;\n\t"
            "WAIT_DONE_%=:\n\t}"
            :: "r"(mbar), "r"(parity) : "memory");
    }
}

// ---------------------------------------------------------------------------
// Fused: zero degree counters + convert X and W to fp16.
__global__ void prep(const float* __restrict__ X, const float* __restrict__ W,
                     int x4, int w4, int n_nodes, int n_edges) {
    int i = blockIdx.x * blockDim.x + threadIdx.x;
    if (i < n_nodes) g_dv[i] = 0;
    if (i < n_edges) g_de[i] = 0;
    if (i < x4) {
        float4 v = ((const float4*)X)[i];
        __half2 a = __floats2half2_rn(v.x, v.y);
        __half2 b = __floats2half2_rn(v.z, v.w);
        uint2 p; p.x = *(unsigned*)&a; p.y = *(unsigned*)&b;
        ((uint2*)g_Xh)[i] = p;
    } else if (i < x4 + w4) {
        int j = i - x4;
        float4 v = ((const float4*)W)[j];
        __half2 a = __floats2half2_rn(v.x, v.y);
        __half2 b = __floats2half2_rn(v.z, v.w);
        uint2 p; p.x = *(unsigned*)&a; p.y = *(unsigned*)&b;
        ((uint2*)g_Wh)[j] = p;
    }
}

// One block per row of H. The 20KB contiguous row is fetched with a SINGLE
// cp.async.bulk (TMA path — bypasses per-thread LDG/L1tex machinery, whose
// measured ceiling here was ~4.5TB/s across 5 scheduling variants). Threads
// then scan from SMEM (conflict-free LDS.128) with the proven warp-scan/emit,
// and drain CSR/CSC with block-parallel atomics.
__global__ __launch_bounds__(256) void build_sparse(const float* __restrict__ H,
                                                    int n_edges) {
    __shared__ __align__(16) float s_row[MAX_E + 8];
    __shared__ __align__(8) unsigned long long s_mbar;
    __shared__ int s_cnt;
    __shared__ int s_list[LIST_CAP];

    int n = blockIdx.x;
    int tid = threadIdx.x;
    int lane = tid & 31;
    uint32_t mbar = smem_u32(&s_mbar);
    uint32_t bytes = (uint32_t)n_edges * 4u;

    if (tid == 0) {
        s_cnt = 0;
        asm volatile("mbarrier.init.shared.b64 [%0], 1;" :: "r"(mbar) : "memory");
        asm volatile("fence.proxy.async.shared::cta;" ::: "memory");
        asm volatile("mbarrier.arrive.expect_tx.shared.b64 _, [%0], %1;"
                     :: "r"(mbar), "r"(bytes) : "memory");
        asm volatile(
            "cp.async.bulk.shared::cta.global.mbarrier::complete_tx::bytes "
            "[%0], [%1], %2, [%3];"
            :: "r"(smem_u32(s_row)), "l"(H + (size_t)n * n_edges),
               "r"(bytes), "r"(mbar) : "memory");
    }
    __syncthreads();                 // all threads see the init before waiting
    mbar_wait_parity(mbar, 0);

    // ---- scan from SMEM: warp-uniform trips, warp scan, emit to s_list ----
    int nq = n_edges >> 2;           // 1250 quads (float4)
    const float4* rowq = (const float4*)s_row;
    const float4 z4 = make_float4(0.f, 0.f, 0.f, 0.f);
    int iters = (nq + 255) / 256;    // uniform: 5

    for (int it = 0; it < iters; it++) {
        int i0 = it * 256 + tid;
        float4 v0 = (i0 < nq) ? rowq[i0] : z4;

        int c = (v0.x != 0.f) + (v0.y != 0.f) + (v0.z != 0.f) + (v0.w != 0.f);

        int pre = c;
        #pragma unroll
        for (int d = 1; d < 32; d <<= 1) {
            int t = __shfl_up_sync(0xffffffffu, pre, d);
            if (lane >= d) pre += t;
        }
        int total = __shfl_sync(0xffffffffu, pre, 31);
        if (total) {
            int base = 0;
            if (lane == 31) base = atomicAdd(&s_cnt, total);
            base = __shfl_sync(0xffffffffu, base, 31);
            int p = base + pre - c;
            int eb = i0 << 2;
            if (v0.x != 0.f) { if (p < LIST_CAP) s_list[p] = eb;     p++; }
            if (v0.y != 0.f) { if (p < LIST_CAP) s_list[p] = eb + 1; p++; }
            if (v0.z != 0.f) { if (p < LIST_CAP) s_list[p] = eb + 2; p++; }
            if (v0.w != 0.f) { if (p < LIST_CAP) s_list[p] = eb + 3; p++; }
        }
    }
    __syncthreads();

    int cnt = min(s_cnt, LIST_CAP);
    if (tid == 0) g_dv[n] = min(cnt, NODE_CAP);
    for (int t = tid; t < cnt; t += blockDim.x) {
        int e = s_list[t];
        if (t < NODE_CAP) g_csr[n * NODE_CAP + t] = e;
        int q = atomicAdd(&g_de[e], 1);
        if (q < EDGE_CAP) g_csc[e * EDGE_CAP + q] = n;
    }
}

// 16 edges per block. Phase 1: warp w gathers S[w] with 4 independent
// LDG.128 in flight per lane (launch_bounds(512,2) -> 64-reg budget).
// Phase 2: HMMA projection. Phase 3: /DE, store fp16.
__global__ __launch_bounds__(512, 2) void gather_mma(int n_edges) {
    __shared__ __half s_h[EPB][FT];
    __shared__ float  s_C[EPB][FT];

    int w = threadIdx.x >> 5;
    int lane = threadIdx.x & 31;
    int e0 = blockIdx.x * EPB;
    int e = e0 + w;

    // ---- phase 1: gather ----
    int hw = lane >> 4;        // half-warp -> node parity
    int fl = lane & 15;        // feature lane: 8 features
    if (e < n_edges) {
        int cnt = min(g_de[e], EDGE_CAP);
        const int* __restrict__ nodes = g_csc + e * EDGE_CAP;
        float acc[8];
        #pragma unroll
        for (int j = 0; j < 8; j++) acc[j] = 0.f;

        int i = hw;
        for (; i + 8 <= cnt; i += 8) {   // 4 nodes per half-warp per iter
            int n0 = nodes[i];
            int n1 = nodes[i + 2];
            int n2 = nodes[i + 4];
            int n3 = nodes[i + 6];
            uint4 p0 = ((const uint4*)(g_Xh + (size_t)n0 * FT))[fl];
            uint4 p1 = ((const uint4*)(g_Xh + (size_t)n1 * FT))[fl];
            uint4 p2 = ((const uint4*)(g_Xh + (size_t)n2 * FT))[fl];
            uint4 p3 = ((const uint4*)(g_Xh + (size_t)n3 * FT))[fl];
            __half2* h0 = (__half2*)&p0;
            __half2* h1 = (__half2*)&p1;
            __half2* h2 = (__half2*)&p2;
            __half2* h3 = (__half2*)&p3;
            #pragma unroll
            for (int q = 0; q < 4; q++) {
                float2 f0 = __half22float2(h0[q]);
                float2 f1 = __half22float2(h1[q]);
                float2 f2 = __half22float2(h2[q]);
                float2 f3 = __half22float2(h3[q]);
                acc[2 * q]     += (f0.x + f1.x) + (f2.x + f3.x);
                acc[2 * q + 1] += (f0.y + f1.y) + (f2.y + f3.y);
            }
        }
        for (; i < cnt; i += 2) {
            int n = nodes[i];
            uint4 p = ((const uint4*)(g_Xh + (size_t)n * FT))[fl];
            __half2* hp = (__half2*)&p;
            #pragma unroll
            for (int q = 0; q < 4; q++) {
                float2 f = __half22float2(hp[q]);
                acc[2 * q]     += f.x;
                acc[2 * q + 1] += f.y;
            }
        }
        #pragma unroll
        for (int j = 0; j < 8; j++)
            acc[j] += __shfl_xor_sync(0xffffffffu, acc[j], 16);
        if (hw == 0) {
            uint4 o;
            __half2 h0 = __floats2half2_rn(acc[0], acc[1]);
            __half2 h1 = __floats2half2_rn(acc[2], acc[3]);
            __half2 h2 = __floats2half2_rn(acc[4], acc[5]);
            __half2 h3 = __floats2half2_rn(acc[6], acc[7]);
            o.x = *(unsigned*)&h0; o.y = *(unsigned*)&h1;
            o.z = *(unsigned*)&h2; o.w = *(unsigned*)&h3;
            ((uint4*)&s_h[w][0])[fl] = o;
        }
    } else {
        if (lane < 16) ((uint4*)&s_h[w][0])[lane] = make_uint4(0, 0, 0, 0);
    }
    __syncthreads();

    // ---- phase 2: [16,128] x [128,128] HMMA ----
    if (w < 8) {
        wmma::fragment<wmma::accumulator, 16, 16, 16, float> c;
        wmma::fill_fragment(c, 0.f);
        #pragma unroll
        for (int k = 0; k < FT; k += 16) {
            wmma::fragment<wmma::matrix_a, 16, 16, 16, __half, wmma::row_major> a;
            wmma::fragment<wmma::matrix_b, 16, 16, 16, __half, wmma::row_major> b;
            wmma::load_matrix_sync(a, &s_h[0][k], FT);
            wmma::load_matrix_sync(b, g_Wh + k * FT + w * 16, FT);
            wmma::mma_sync(c, a, b, c);
        }
        wmma::store_matrix_sync(&s_C[0][w * 16], c, FT, wmma::mem_row_major);
    }
    __syncthreads();

    // ---- phase 3: epilogue M = C / DE ----
    for (int idx = threadIdx.x; idx < EPB * FT; idx += 512) {
        int r = idx >> 7, j = idx & (FT - 1);
        int e2 = e0 + r;
        if (e2 < n_edges) {
            int de = g_de[e2];
            float m = (de > 0) ? s_C[r][j] / (float)de : 0.f;
            g_Mh[(size_t)e2 * FT + j] = __float2half(m);
        }
    }
}

// out[n] = relu( (sum_{e in node n} M[e]) / dv[n] + bias ).
// NOTE: no min-blocks bound — regs=32 / 16 blocks/SM measured 30.2-30.9us;
// capping to 8 blocks (regs=60) measured 45.6us. Warp count wins here.
__global__ __launch_bounds__(FT) void scatter_out(const float* __restrict__ bias,
                                                  float* __restrict__ out) {
    int n = blockIdx.x;
    int t = threadIdx.x;
    int lane = t & 31;
    int g = t >> 5;
    int cnt = g_dv[n];
    const int* __restrict__ edges = g_csr + n * NODE_CAP;

    float4 acc = make_float4(0.f, 0.f, 0.f, 0.f);
    int i = g;
    for (; i + 16 <= cnt; i += 16) {   // 4 edges per group per iter
        int e0 = edges[i];
        int e1 = edges[i + 4];
        int e2 = edges[i + 8];
        int e3 = edges[i + 12];
        uint2 p0 = ((const uint2*)(g_Mh + (size_t)e0 * FT))[lane];
        uint2 p1 = ((const uint2*)(g_Mh + (size_t)e1 * FT))[lane];
        uint2 p2 = ((const uint2*)(g_Mh + (size_t)e2 * FT))[lane];
        uint2 p3 = ((const uint2*)(g_Mh + (size_t)e3 * FT))[lane];
        float2 a0 = __half22float2(*(__half2*)&p0.x), b0 = __half22float2(*(__half2*)&p0.y);
        float2 a1 = __half22float2(*(__half2*)&p1.x), b1 = __half22float2(*(__half2*)&p1.y);
        float2 a2 = __half22float2(*(__half2*)&p2.x), b2 = __half22float2(*(__half2*)&p2.y);
        float2 a3 = __half22float2(*(__half2*)&p3.x), b3 = __half22float2(*(__half2*)&p3.y);
        acc.x += (a0.x + a1.x) + (a2.x + a3.x);
        acc.y += (a0.y + a1.y) + (a2.y + a3.y);
        acc.z += (b0.x + b1.x) + (b2.x + b3.x);
        acc.w += (b0.y + b1.y) + (b2.y + b3.y);
    }
    for (; i < cnt; i += 4) {
        int e = edges[i];
        uint2 p = ((const uint2*)(g_Mh + (size_t)e * FT))[lane];
        float2 f0 = __half22float2(*(__half2*)&p.x);
        float2 f1 = __half22float2(*(__half2*)&p.y);
        acc.x += f0.x; acc.y += f0.y; acc.z += f1.x; acc.w += f1.y;
    }

    __shared__ float part[4][FT];
    ((float4*)part[g])[lane] = acc;
    __syncthreads();
    float v = (part[0][t] + part[1][t]) + (part[2][t] + part[3][t]);
    v = (cnt > 0) ? v / (float)cnt : 0.f;
    v += bias[t];
    out[(size_t)n * FT + t] = v > 0.f ? v : 0.f;
}

// ---------------------------------------------------------------------------
extern "C" void kernel_launch(void* const* d_in, const int* in_sizes, int n_in,
                              void* d_out, int out_size) {
    const float* X  = (const float*)d_in[0];   // [N, 128]
    const float* H  = (const float*)d_in[1];   // [N, E]
    const float* Wt = (const float*)d_in[2];   // [128, 128]
    const float* bs = (const float*)d_in[3];   // [128]
    float* out = (float*)d_out;                // [N, 128]

    int n_nodes = in_sizes[0] / FT;            // 20000
    int n_edges = in_sizes[1] / n_nodes;       // 5000
    if (n_nodes > MAX_N) n_nodes = MAX_N;
    if (n_edges > MAX_E) n_edges = MAX_E;

    int x4 = n_nodes * FT / 4;
    int w4 = FT * FT / 4;
    int ptot = x4 + w4;
    if (n_nodes > ptot) ptot = n_nodes;
    prep<<<(ptot + 255) / 256, 256>>>(X, Wt, x4, w4, n_nodes, n_edges);
    build_sparse<<<n_nodes, 256>>>(H, n_edges);
    gather_mma<<<(n_edges + EPB - 1) / EPB, 512>>>(n_edges);
    scatter_out<<<n_nodes, FT>>>(bs, out);
}